// round 8
// baseline (speedup 1.0000x reference)
#include <cuda_runtime.h>

// ---------------------------------------------------------------------------
// NCA step, tensor-core formulation (mma.sync m16n8k8 tf32):
//   p = depthwise [ident, sobel_x, sobel_y]  (16ch -> 48ch)   [scalar, smem]
//   h = relu(W1 p + b1)    GEMM1 [128px x 48] * [48 x 128]    [mma, fp32 acc]
//   dx = W2 h              GEMM2 [128px x 128] * [128 x 16]   [mma, K split 4 warps]
//   x_new = x + dx*mask -> g_xnew ; kernel2 applies alive gating.
// ---------------------------------------------------------------------------

#define Bn 32
#define Cn 16
#define Hn 256
#define Wn 256
#define THRESH 0.1f

__device__ float g_xnew[Bn * Cn * Hn * Wn];

typedef unsigned int u32;

__device__ __forceinline__ u32 f2tf(float f) {
    u32 r; asm("cvt.rna.tf32.f32 %0, %1;" : "=r"(r) : "f"(f)); return r;
}

__device__ __forceinline__ void mma_tf32(float& d0, float& d1, float& d2, float& d3,
                                         u32 a0, u32 a1, u32 a2, u32 a3,
                                         u32 b0, u32 b1) {
    asm volatile("mma.sync.aligned.m16n8k8.row.col.f32.tf32.tf32.f32 "
                 "{%0,%1,%2,%3}, {%4,%5,%6,%7}, {%8,%9}, {%0,%1,%2,%3};"
                 : "+f"(d0), "+f"(d1), "+f"(d2), "+f"(d3)
                 : "r"(a0), "r"(a1), "r"(a2), "r"(a3), "r"(b0), "r"(b1));
}

// smem layout (bytes):
//   [0,      34816) dxs [4][128][17] f32   (xs [16][6][36] f32, 13824 B, overlays start)
//   [34816,  61440) p   [128][52] u32 bits (stride 52 -> conflict-free A-frag loads)
//   [61440,  88064) w1s [128][52] tf32
//   [88064,  96512) w2s [16][132] tf32
//   [96512,  97024) b1s [128] f32
#define SM_P   (34816 / 4)
#define SM_W1  (61440 / 4)
#define SM_W2  (88064 / 4)
#define SM_B1  (96512 / 4)
#define SMEM_BYTES 97024

extern __shared__ u32 sm[];

__global__ void __launch_bounds__(128)
nca_update(const float* __restrict__ x, const float* __restrict__ w1,
           const float* __restrict__ b1, const float* __restrict__ w2,
           const u32* __restrict__ um)
{
    const int tid = threadIdx.x;
    const int b  = blockIdx.z;
    const int y0 = blockIdx.y * 4;
    const int x0 = blockIdx.x * 32;

    float* xs  = (float*)sm;            // [16][6][36], transient
    u32*   ps  = sm + SM_P;             // [128][52]
    u32*   w1s = sm + SM_W1;            // [128][52]
    u32*   w2s = sm + SM_W2;            // [16][132]
    float* b1s = (float*)(sm + SM_B1);  // [128]
    float* dxs = (float*)sm;            // [4][128][17], written after xs is dead

    // ---- load x tile + 1-halo (rows y0-1..y0+4, cols x0-1..x0+32, 16 ch) ----
    const float* xb = x + ((long long)(b * Cn) << 16);
    for (int i = tid; i < 16 * 6 * 34; i += 128) {
        int c = i / 204, rem = i - c * 204;
        int r = rem / 34, col = rem - r * 34;
        int gy = y0 - 1 + r, gx = x0 - 1 + col;
        float v = 0.f;                              // conv 'SAME' zero pad
        if ((unsigned)gy < Hn && (unsigned)gx < Wn) v = xb[(c << 16) + (gy << 8) + gx];
        xs[c * 216 + r * 36 + col] = v;
    }
    __syncthreads();

    // ---- perception: one pixel per thread; p stored as raw f32 bits ----
    // (mma reads them tf32-truncated; ident cols stay exact for the residual)
    const int pr = tid >> 5, pc = tid & 31;
    {
        u32* pp = ps + tid * 52;
#pragma unroll
        for (int c = 0; c < 16; ++c) {
            const float* q = xs + c * 216 + pr * 36 + pc;
            float v00 = q[0],  v01 = q[1],  v02 = q[2];
            float v10 = q[36], v11 = q[37], v12 = q[38];
            float v20 = q[72], v21 = q[73], v22 = q[74];
            float sx = (v02 - v00 + 2.f * (v12 - v10) + v22 - v20) * 0.125f;
            float sy = (v20 - v00 + 2.f * (v21 - v01) + v22 - v02) * 0.125f;
            pp[3 * c + 0] = __float_as_uint(v11);
            pp[3 * c + 1] = __float_as_uint(sx);
            pp[3 * c + 2] = __float_as_uint(sy);
        }
    }
    // ---- stage weights (rna-rounded tf32) ----
    for (int i = tid; i < 6144; i += 128) {        // w1 [128][48] row-major
        int n = i / 48, k = i - n * 48;
        w1s[n * 52 + k] = f2tf(w1[i]);
    }
    for (int i = tid; i < 2048; i += 128) {        // w2 [16][128] row-major
        int n = i >> 7, k = i & 127;
        w2s[n * 132 + k] = f2tf(w2[i]);
    }
    b1s[tid] = b1[tid];
    __syncthreads();

    const int lane = tid & 31, wid = tid >> 5;
    const int g = lane >> 2, tig = lane & 3;
    const int wb = wid * 32;                       // this warp's hidden-col base

    // B1 fragments: B[k][n] = w1[n][k]; b0=(row k=tig, col n=g), b1 k+4
    u32 bf[6][4][2];
#pragma unroll
    for (int kt = 0; kt < 6; ++kt)
#pragma unroll
        for (int nn = 0; nn < 4; ++nn) {
            int n = wb + nn * 8 + g;
            bf[kt][nn][0] = w1s[n * 52 + kt * 8 + tig];
            bf[kt][nn][1] = w1s[n * 52 + kt * 8 + tig + 4];
        }
    // B2 fragments: B[k=hcol][n=ch] = w2[ch][hcol], K local to this warp
    u32 b2f[4][2][2];
#pragma unroll
    for (int kk = 0; kk < 4; ++kk)
#pragma unroll
        for (int n2 = 0; n2 < 2; ++n2) {
            int n = n2 * 8 + g;
            b2f[kk][n2][0] = w2s[n * 132 + wb + kk * 8 + tig];
            b2f[kk][n2][1] = w2s[n * 132 + wb + kk * 8 + tig + 4];
        }
    // bias for D1 init: D cols are hidden units; c0 col = 2*tig, c1 = +1
    float bs[4][2];
#pragma unroll
    for (int nn = 0; nn < 4; ++nn) {
        int n = wb + nn * 8 + 2 * tig;
        bs[nn][0] = b1s[n];
        bs[nn][1] = b1s[n + 1];
    }

    // mask (early, hides LDG latency behind the mma loop)
    const int gy = y0 + pr, gx = x0 + pc;
    const float mfl = um[(b << 16) + (gy << 8) + gx] ? 1.f : 0.f;

    const int srcA = (lane & ~3) | (tig >> 1);     // D->A transpose shuffle sources
    const int srcB = srcA + 2;
    const bool odd = (tig & 1);

#pragma unroll 1
    for (int m = 0; m < 8; ++m) {                  // 8 m-tiles of 16 pixels
        // A1 fragments from p: a0=(row g, col tig), a1 row+8, a2 col+4, a3 both
        u32 af[6][4];
        const u32* prow0 = ps + (m * 16 + g) * 52;
        const u32* prow1 = prow0 + 8 * 52;
#pragma unroll
        for (int kt = 0; kt < 6; ++kt) {
            af[kt][0] = prow0[kt * 8 + tig];
            af[kt][1] = prow1[kt * 8 + tig];
            af[kt][2] = prow0[kt * 8 + tig + 4];
            af[kt][3] = prow1[kt * 8 + tig + 4];
        }
        float dq0[4] = {0.f, 0.f, 0.f, 0.f};       // GEMM2 acc, ch 0..7
        float dq1[4] = {0.f, 0.f, 0.f, 0.f};       // GEMM2 acc, ch 8..15
#pragma unroll
        for (int nn = 0; nn < 4; ++nn) {           // hidden n-tile == GEMM2 k-chunk
            float d0 = bs[nn][0], d1 = bs[nn][1], d2 = bs[nn][0], d3 = bs[nn][1];
#pragma unroll
            for (int kt = 0; kt < 6; ++kt)
                mma_tf32(d0, d1, d2, d3,
                         af[kt][0], af[kt][1], af[kt][2], af[kt][3],
                         bf[kt][nn][0], bf[kt][nn][1]);
            d0 = fmaxf(d0, 0.f); d1 = fmaxf(d1, 0.f);
            d2 = fmaxf(d2, 0.f); d3 = fmaxf(d3, 0.f);
            // D-frag (cols 2t,2t+1) -> A-frag (cols t, t+4) via shuffles
            float t0 = __shfl_sync(0xffffffffu, d0, srcA);
            float t1 = __shfl_sync(0xffffffffu, d1, srcA);
            float t2 = __shfl_sync(0xffffffffu, d2, srcA);
            float t3 = __shfl_sync(0xffffffffu, d3, srcA);
            float u0 = __shfl_sync(0xffffffffu, d0, srcB);
            float u1 = __shfl_sync(0xffffffffu, d1, srcB);
            float u2 = __shfl_sync(0xffffffffu, d2, srcB);
            float u3 = __shfl_sync(0xffffffffu, d3, srcB);
            u32 a0 = __float_as_uint(odd ? t1 : t0);
            u32 a1 = __float_as_uint(odd ? t3 : t2);
            u32 a2 = __float_as_uint(odd ? u1 : u0);
            u32 a3 = __float_as_uint(odd ? u3 : u2);
            mma_tf32(dq0[0], dq0[1], dq0[2], dq0[3], a0, a1, a2, a3,
                     b2f[nn][0][0], b2f[nn][0][1]);
            mma_tf32(dq1[0], dq1[1], dq1[2], dq1[3], a0, a1, a2, a3,
                     b2f[nn][1][0], b2f[nn][1][1]);
        }
        // stage this warp's partial dx (its 32 hidden cols) for the m-tile
        float* dst  = dxs + wid * 2176 + (m * 16 + g) * 17;
        float* dst2 = dst + 8 * 17;
        dst[2 * tig]      = dq0[0];  dst[2 * tig + 1]      = dq0[1];
        dst[8 + 2 * tig]  = dq1[0];  dst[8 + 2 * tig + 1]  = dq1[1];
        dst2[2 * tig]     = dq0[2];  dst2[2 * tig + 1]     = dq0[3];
        dst2[8 + 2 * tig] = dq1[2];  dst2[8 + 2 * tig + 1] = dq1[3];
    }
    __syncthreads();

    // ---- reduce the 4 warp partials, apply mask + residual, write x_new ----
    const u32* pp = ps + tid * 52;
    const int obase = (b << 20) + (gy << 8) + gx;
#pragma unroll
    for (int ch = 0; ch < 16; ++ch) {
        float s = dxs[0 * 2176 + tid * 17 + ch] + dxs[1 * 2176 + tid * 17 + ch]
                + dxs[2 * 2176 + tid * 17 + ch] + dxs[3 * 2176 + tid * 17 + ch];
        float xv = __uint_as_float(pp[3 * ch]);    // exact x (ident channel)
        g_xnew[obase + (ch << 16)] = xv + s * mfl;
    }
}

// ---------------------------------------------------------------------------
// Kernel 2: alive gating.  out = x_new * (maxpool3(x[3])>thr & maxpool3(x_new[3])>thr)
// ---------------------------------------------------------------------------
__global__ void __launch_bounds__(256)
nca_mask(const float* __restrict__ x, float* __restrict__ out)
{
    __shared__ float s3[10][136];
    __shared__ float sn3[10][136];

    const int b  = blockIdx.z;
    const int y0 = blockIdx.y * 8;
    const int x0 = blockIdx.x * 128;
    const int tid = threadIdx.y * 32 + threadIdx.x;
    const int plane = ((b * Cn + 3) << 16);

    for (int i = tid; i < 10 * 130; i += 256) {
        int r = i / 130, j = i - r * 130;
        int gy = y0 - 1 + r, gx = x0 - 1 + j;
        float v0 = -1e30f, v1 = -1e30f;
        if ((unsigned)gy < Hn && (unsigned)gx < Wn) {
            int idx = plane + (gy << 8) + gx;
            v0 = x[idx];
            v1 = g_xnew[idx];
        }
        s3[r][j]  = v0;
        sn3[r][j] = v1;
    }
    __syncthreads();

    const int ty = threadIdx.y, tx = threadIdx.x;
    float c0[6], c1[6];
#pragma unroll
    for (int jj = 0; jj < 6; ++jj) {
        int j = 4 * tx + jj;
        c0[jj] = fmaxf(fmaxf(s3[ty][j],  s3[ty + 1][j]),  s3[ty + 2][j]);
        c1[jj] = fmaxf(fmaxf(sn3[ty][j], sn3[ty + 1][j]), sn3[ty + 2][j]);
    }
    float f[4];
#pragma unroll
    for (int i = 0; i < 4; ++i) {
        float m0 = fmaxf(fmaxf(c0[i], c0[i + 1]), c0[i + 2]);
        float m1 = fmaxf(fmaxf(c1[i], c1[i + 1]), c1[i + 2]);
        f[i] = (m0 > THRESH && m1 > THRESH) ? 1.0f : 0.0f;
    }

    const int gy = y0 + ty, gxA = x0 + 4 * tx;
    const int idx = (b << 20) + (gy << 8) + gxA;
#pragma unroll
    for (int c = 0; c < 16; ++c) {
        float4 v = *(const float4*)(g_xnew + idx + (c << 16));
        v.x *= f[0]; v.y *= f[1]; v.z *= f[2]; v.w *= f[3];
        *(float4*)(out + idx + (c << 16)) = v;
    }
}

// ---------------------------------------------------------------------------
extern "C" void kernel_launch(void* const* d_in, const int* in_sizes, int n_in,
                              void* d_out, int out_size)
{
    const float* x  = (const float*)d_in[0];
    // d_in[1] = sobel kernel: fixed by construction, hardcoded in perception
    const float* w1 = (const float*)d_in[2];
    const float* b1 = (const float*)d_in[3];
    const float* w2 = (const float*)d_in[4];
    const u32*   um = (const u32*)d_in[5];
    float* out = (float*)d_out;

    cudaFuncSetAttribute(nca_update, cudaFuncAttributeMaxDynamicSharedMemorySize, SMEM_BYTES);

    dim3 g1(Wn / 32, Hn / 4, Bn);
    nca_update<<<g1, 128, SMEM_BYTES>>>(x, w1, b1, w2, um);

    dim3 g2(Wn / 128, Hn / 8, Bn), tb2(32, 8);
    nca_mask<<<g2, tb2>>>(x, out);
}